// round 6
// baseline (speedup 1.0000x reference)
#include <cuda_runtime.h>
#include <cuda_bf16.h>
#include <cuda_fp16.h>
#include <math.h>
#include <stdint.h>

#define B_    2
#define T_    4096
#define HID_  2048
#define H_    16
#define HKV_  4
#define D_    128
#define NB_   64
#define QKVN_ 3072
#define SCALE_ 0.088388347648318447f
#define NEG_  (-1.0e9f)
#define MTOT  (B_*T_)   // 8192

// ---------------- scratch ----------------------------------------------------
__device__ float g_qkv[(size_t)MTOT * QKVN_];
__device__ __half g_hs_hi[(size_t)MTOT*HID_];
__device__ __half g_hs_lo[(size_t)MTOT*HID_];
__device__ __half g_w1_hi[(size_t)QKVN_*HID_];
__device__ __half g_w2_hi[(size_t)HID_*HID_];
__device__ __half g_at_hi[(size_t)MTOT*HID_];
__device__ __half g_at_lo[(size_t)MTOT*HID_];

// ---------------- PTX helpers ----------------------------------------------
__device__ __forceinline__ uint32_t smem_u32(const void* p) {
    uint32_t a;
    asm("{ .reg .u64 t; cvta.to.shared.u64 t, %1; cvt.u32.u64 %0, t; }"
        : "=r"(a) : "l"(p));
    return a;
}

#define CP_ASYNC16(dst, src) \
    asm volatile("cp.async.cg.shared.global [%0], [%1], 16;\n" \
                 :: "r"(dst), "l"(src))
#define CP_COMMIT() asm volatile("cp.async.commit_group;\n" ::: "memory")
#define CP_WAIT(n)  asm volatile("cp.async.wait_group %0;\n" :: "n"(n) : "memory")

#define LDMATRIX_X4(r0, r1, r2, r3, addr) \
    asm volatile("ldmatrix.sync.aligned.m8n8.x4.shared.b16 {%0,%1,%2,%3}, [%4];" \
                 : "=r"(r0), "=r"(r1), "=r"(r2), "=r"(r3) : "r"(addr))

#define LDMATRIX_X2(r0, r1, addr) \
    asm volatile("ldmatrix.sync.aligned.m8n8.x2.shared.b16 {%0,%1}, [%2];" \
                 : "=r"(r0), "=r"(r1) : "r"(addr))

#define LDMATRIX_X4T(r0, r1, r2, r3, addr) \
    asm volatile("ldmatrix.sync.aligned.m8n8.x4.trans.shared.b16 {%0,%1,%2,%3}, [%4];" \
                 : "=r"(r0), "=r"(r1), "=r"(r2), "=r"(r3) : "r"(addr))

#define MMA_BF16(d, a, b0, b1) \
    asm volatile("mma.sync.aligned.m16n8k16.row.col.f32.bf16.bf16.f32 " \
                 "{%0,%1,%2,%3}, {%4,%5,%6,%7}, {%8,%9}, {%0,%1,%2,%3};" \
                 : "+f"((d)[0]), "+f"((d)[1]), "+f"((d)[2]), "+f"((d)[3]) \
                 : "r"((a)[0]), "r"((a)[1]), "r"((a)[2]), "r"((a)[3]), \
                   "r"(b0), "r"(b1))

#define MMA_F16(d, a, b0, b1) \
    asm volatile("mma.sync.aligned.m16n8k16.row.col.f32.f16.f16.f32 " \
                 "{%0,%1,%2,%3}, {%4,%5,%6,%7}, {%8,%9}, {%0,%1,%2,%3};" \
                 : "+f"((d)[0]), "+f"((d)[1]), "+f"((d)[2]), "+f"((d)[3]) \
                 : "r"((a)[0]), "r"((a)[1]), "r"((a)[2]), "r"((a)[3]), \
                   "r"(b0), "r"(b1))

// float4 -> bf16 hi x4 + lo x4
__device__ __forceinline__ void cvt4(float4 v, uint2& H, uint2& L) {
    float a[4] = {v.x, v.y, v.z, v.w};
    __nv_bfloat16 h[4], l[4];
    #pragma unroll
    for (int j = 0; j < 4; j++) {
        h[j] = __float2bfloat16_rn(a[j]);
        l[j] = __float2bfloat16_rn(a[j] - __bfloat162float(h[j]));
    }
    union { __nv_bfloat162 b2[2]; uint2 u; } uh, ul;
    uh.b2[0] = __halves2bfloat162(h[0], h[1]);
    uh.b2[1] = __halves2bfloat162(h[2], h[3]);
    ul.b2[0] = __halves2bfloat162(l[0], l[1]);
    ul.b2[1] = __halves2bfloat162(l[2], l[3]);
    H = uh.u; L = ul.u;
}

// float4 -> fp16 hi x4 + lo x4
__device__ __forceinline__ void cvt4h(float4 v, uint2& H, uint2& L) {
    float a[4] = {v.x, v.y, v.z, v.w};
    __half h[4], l[4];
    #pragma unroll
    for (int j = 0; j < 4; j++) {
        h[j] = __float2half_rn(a[j]);
        l[j] = __float2half_rn(a[j] - __half2float(h[j]));
    }
    union { __half2 h2[2]; uint2 u; } uh, ul;
    uh.h2[0] = __halves2half2(h[0], h[1]);
    uh.h2[1] = __halves2half2(h[2], h[3]);
    ul.h2[0] = __halves2half2(l[0], l[1]);
    ul.h2[1] = __halves2half2(l[2], l[3]);
    H = uh.u; L = ul.u;
}

// ---------------------------------------------------------------------------
// fp32 -> fp16 hi + residual lo (8 elems/thread)
// ---------------------------------------------------------------------------
__global__ void cvt_kernel(const float* __restrict__ in,
                           __half* __restrict__ hi,
                           __half* __restrict__ lo, int n)
{
    size_t i = ((size_t)blockIdx.x * blockDim.x + threadIdx.x) * 8;
    if (i >= (size_t)n) return;
    uint2 H0, L0, H1, L1;
    cvt4h(*(const float4*)(in + i),     H0, L0);
    cvt4h(*(const float4*)(in + i + 4), H1, L1);
    *(uint4*)(hi + i) = make_uint4(H0.x, H0.y, H1.x, H1.y);
    *(uint4*)(lo + i) = make_uint4(L0.x, L0.y, L1.x, L1.y);
}

// fp32 -> fp16 hi only (weights: residual not needed, A-side is corrected)
__global__ void cvt_hi_kernel(const float* __restrict__ in,
                              __half* __restrict__ hi, int n)
{
    size_t i = ((size_t)blockIdx.x * blockDim.x + threadIdx.x) * 8;
    if (i >= (size_t)n) return;
    float4 v0 = *(const float4*)(in + i);
    float4 v1 = *(const float4*)(in + i + 4);
    float a[8] = {v0.x, v0.y, v0.z, v0.w, v1.x, v1.y, v1.z, v1.w};
    union { __half2 h2[4]; uint4 u; } uh;
    #pragma unroll
    for (int j = 0; j < 4; j++)
        uh.h2[j] = __halves2half2(__float2half_rn(a[2 * j]),
                                  __float2half_rn(a[2 * j + 1]));
    *(uint4*)(hi + i) = uh.u;
}

// ---------------------------------------------------------------------------
// fp16 2-term GEMM: C = (Ah + Al) * Bh^T.  Only B's fp16 rounding remains
// (~2.8e-4 rms).  CTA 128x128, BK=64, 8 warps (64x32), 3-stage cp.async.
// smem/stage: Ah 16KB | Al 16KB | Bh 16KB.
// ---------------------------------------------------------------------------
#define GEMM_SMEM (3 * 49152)

__global__ void __launch_bounds__(256, 1) gemm_f16x2(
    const __half* __restrict__ Ah, const __half* __restrict__ Al,
    const __half* __restrict__ Bh,
    float* __restrict__ C, int K, int ldc)
{
    extern __shared__ char smem[];
    const int tid  = threadIdx.x;
    const int lane = tid & 31;
    const int wid  = tid >> 5;
    const int m0 = blockIdx.y * 128;
    const int n0 = blockIdx.x * 128;
    const int warpM = (wid >> 2) * 64;
    const int warpN = (wid & 3) * 32;

    const uint32_t sb = smem_u32(smem);

    uint32_t soff[4]; uint32_t grow[4]; uint32_t gcol[4];
    #pragma unroll
    for (int t = 0; t < 4; t++) {
        int idx = tid + t * 256;
        int row = idx >> 3, u = idx & 7;
        uint32_t bo = (uint32_t)(row * 128 + u * 16);
        soff[t] = bo ^ ((bo >> 3) & 0x70);
        grow[t] = (uint32_t)row;
        gcol[t] = (uint32_t)(u * 16);
    }

    const int NCH = K >> 6;
    const size_t rs = (size_t)K * 2;
    const char* pAh = (const char*)(Ah + (size_t)m0 * K);
    const char* pAl = (const char*)(Al + (size_t)m0 * K);
    const char* pBh = (const char*)(Bh + (size_t)n0 * K);

    auto load_chunk = [&](int c) {
        uint32_t base = sb + (uint32_t)(c % 3) * 49152u;
        size_t co = (size_t)c * 128;
        #pragma unroll
        for (int t = 0; t < 4; t++) {
            size_t go = (size_t)grow[t] * rs + co + gcol[t];
            CP_ASYNC16(base +          soff[t], pAh + go);
            CP_ASYNC16(base + 16384u + soff[t], pAl + go);
            CP_ASYNC16(base + 32768u + soff[t], pBh + go);
        }
        CP_COMMIT();
    };

    const uint32_t lrow  = (uint32_t)(lane & 15);
    const uint32_t lcolb = (uint32_t)((lane >> 4) * 16);
    const uint32_t cx    = ((uint32_t)lrow & 7) << 4;
    const uint32_t aRowOff = (uint32_t)(warpM + lrow) * 128;
    const uint32_t bRowOff = (uint32_t)(warpN + lrow) * 128;

    float d[4][4][4];
    #pragma unroll
    for (int mi = 0; mi < 4; mi++)
        #pragma unroll
        for (int ni = 0; ni < 4; ni++)
            #pragma unroll
            for (int r = 0; r < 4; r++) d[mi][ni][r] = 0.f;

    load_chunk(0);
    if (NCH > 1) load_chunk(1);
    if (NCH > 2) load_chunk(2);

    for (int c = 0; c < NCH; c++) {
        const int rem = NCH - 1 - c;
        if (rem >= 2)      { CP_WAIT(2); }
        else if (rem == 1) { CP_WAIT(1); }
        else               { CP_WAIT(0); }
        __syncthreads();

        const uint32_t base = sb + (uint32_t)(c % 3) * 49152u;
        #pragma unroll
        for (int kk = 0; kk < 4; kk++) {
            const uint32_t cb = ((uint32_t)(kk * 32) + lcolb) ^ cx;
            uint32_t bh[2][4];
            #pragma unroll
            for (int pj = 0; pj < 2; pj++) {
                uint32_t ab = base + 32768u + bRowOff + (uint32_t)pj * 2048 + cb;
                LDMATRIX_X4(bh[pj][0], bh[pj][1], bh[pj][2], bh[pj][3], ab);
            }
            #pragma unroll
            for (int mi = 0; mi < 4; mi++) {
                uint32_t ah[4], al2[4];
                uint32_t aa = base + aRowOff + (uint32_t)mi * 2048 + cb;
                LDMATRIX_X4(ah[0], ah[1], ah[2], ah[3], aa);
                LDMATRIX_X4(al2[0], al2[1], al2[2], al2[3], aa + 16384u);
                #pragma unroll
                for (int ni = 0; ni < 4; ni++) {
                    const int pj = ni >> 1, j = ni & 1;
                    MMA_F16(d[mi][ni], ah,  bh[pj][j], bh[pj][j + 2]);
                    MMA_F16(d[mi][ni], al2, bh[pj][j], bh[pj][j + 2]);
                }
            }
        }
        __syncthreads();
        if (c + 3 < NCH) load_chunk(c + 3);
    }

    #pragma unroll
    for (int mi = 0; mi < 4; mi++) {
        const int r0 = m0 + warpM + mi * 16 + (lane >> 2);
        #pragma unroll
        for (int ni = 0; ni < 4; ni++) {
            const int cn = n0 + warpN + ni * 8 + (lane & 3) * 2;
            *(float2*)(C + (size_t)r0 * ldc + cn) =
                make_float2(d[mi][ni][0], d[mi][ni][1]);
            *(float2*)(C + (size_t)(r0 + 8) * ldc + cn) =
                make_float2(d[mi][ni][2], d[mi][ni][3]);
        }
    }
}

// ---------------------------------------------------------------------------
// RoPE in-place on g_qkv
// ---------------------------------------------------------------------------
__global__ void rope_kernel(float* __restrict__ qkv,
                            const float* __restrict__ cosb,
                            const float* __restrict__ sinb)
{
    const int gw   = (blockIdx.x * blockDim.x + threadIdx.x) >> 5;
    const int lane = threadIdx.x & 31;
    const int tok  = gw / 20;
    const int hh   = gw % 20;
    if (tok >= MTOT) return;

    float* base = qkv + (size_t)tok * QKVN_ +
                  (hh < 16 ? hh * D_ : 2048 + (hh - 16) * D_);
    const float* cr = cosb + (size_t)tok * 64;
    const float* sr = sinb + (size_t)tok * 64;

    float x1 = base[lane], x2 = base[lane + 32];
    float c1 = cr[lane],  s1 = sr[lane];
    float c2 = cr[lane + 32], s2 = sr[lane + 32];
    base[lane]      = x1 * c1 - x2 * s1;
    base[lane + 32] = x2 * c2 + x1 * s2;
}

// ---------------------------------------------------------------------------
// Tensor-core block-sparse attention (bf16 hi/lo 3-term internally),
// epilogue emits fp16 hi/lo for the Wo GEMM.
// ---------------------------------------------------------------------------
#define OQH 0
#define OQL 17408
#define OKH 34816
#define OKL 52224
#define OVH 69632
#define OVL 87040
#define OSX 104448          // fp32 [64][68]
#define OPH 121856          // bf16 [64][72]
#define OPL 131072
#define OALF 140288
#define OMRW 140544
#define OLRW 140800
#define ATTN_SMEM 141056

__global__ void __launch_bounds__(256) attn_kernel(const float* __restrict__ qkv,
                                                   __half* __restrict__ outh,
                                                   __half* __restrict__ outl)
{
    extern __shared__ char smc[];
    const uint32_t sb = smem_u32(smc);
    float* Sx  = (float*)(smc + OSX);
    __nv_bfloat16* Ph = (__nv_bfloat16*)(smc + OPH);
    __nv_bfloat16* Pl = (__nv_bfloat16*)(smc + OPL);
    float* alf = (float*)(smc + OALF);
    float* mrw = (float*)(smc + OMRW);
    float* lrw = (float*)(smc + OLRW);

    const int tid  = threadIdx.x;
    const int lane = tid & 31;
    const int wid  = tid >> 5;
    const int iblk = blockIdx.x;
    const int h    = blockIdx.y;
    const int b    = blockIdx.z;
    const int hk   = h >> 2;
    const size_t tok0 = (size_t)b * T_ + (size_t)iblk * 64;

    const float* qg = qkv + tok0 * QKVN_ + h * D_;
    for (int f = tid; f < 2048; f += 256) {
        int r = f >> 5, c4 = (f & 31) * 4;
        uint2 Hv, Lv;
        cvt4(*(const float4*)(qg + (size_t)r * QKVN_ + c4), Hv, Lv);
        uint32_t off = (uint32_t)(r * 272 + c4 * 2);
        *(uint2*)(smc + OQH + off) = Hv;
        *(uint2*)(smc + OQL + off) = Lv;
    }
    if (tid < 64) { mrw[tid] = -3.0e38f; lrw[tid] = 0.f; }

    const uint32_t arow  = (uint32_t)(lane & 15);
    const uint32_t acolb = (uint32_t)((lane >> 4) * 16);
    const int qrow = lane >> 2;
    const int qcol = (lane & 3) * 2;

    const int n0 = wid * 8;
    const int miw   = wid >> 1;
    const int nhalf = (wid & 1) * 64;

    float accO[8][4];
    #pragma unroll
    for (int nt = 0; nt < 8; nt++)
        #pragma unroll
        for (int r = 0; r < 4; r++) accO[nt][r] = 0.f;

    for (int s = 0; s < 9; s++) {
        int kb = (s == 0) ? 0 : iblk - 8 + s;
        if (s > 0 && kb <= 0) continue;
        const bool selfb = (kb == iblk);

        __syncthreads();

        const size_t ktok = (size_t)b * T_ + (size_t)kb * 64;
        const float* kg = qkv + ktok * QKVN_ + 2048 + hk * D_;
        const float* vg = kg + 512;
        for (int f = tid; f < 2048; f += 256) {
            int r = f >> 5, c4 = (f & 31) * 4;
            uint32_t off = (uint32_t)(r * 272 + c4 * 2);
            uint2 Hv, Lv;
            cvt4(*(const float4*)(kg + (size_t)r * QKVN_ + c4), Hv, Lv);
            *(uint2*)(smc + OKH + off) = Hv;
            *(uint2*)(smc + OKL + off) = Lv;
            cvt4(*(const float4*)(vg + (size_t)r * QKVN_ + c4), Hv, Lv);
            *(uint2*)(smc + OVH + off) = Hv;
            *(uint2*)(smc + OVL + off) = Lv;
        }
        __syncthreads();

        float sacc[4][4];
        #pragma unroll
        for (int mi = 0; mi < 4; mi++)
            #pragma unroll
            for (int r = 0; r < 4; r++) sacc[mi][r] = 0.f;

        #pragma unroll
        for (int kk = 0; kk < 8; kk++) {
            uint32_t kbh[2], kbl[2];
            {
                uint32_t r = (uint32_t)(n0 + (lane & 7));
                uint32_t cb = (uint32_t)(kk * 32 + ((lane >> 3) & 1) * 16);
                uint32_t ad = sb + r * 272 + cb;
                LDMATRIX_X2(kbh[0], kbh[1], ad + OKH);
                LDMATRIX_X2(kbl[0], kbl[1], ad + OKL);
            }
            #pragma unroll
            for (int mi = 0; mi < 4; mi++) {
                uint32_t qh[4], ql[4];
                uint32_t ad = sb + ((uint32_t)(mi * 16) + arow) * 272 +
                              (uint32_t)(kk * 32) + acolb;
                LDMATRIX_X4(qh[0], qh[1], qh[2], qh[3], ad + OQH);
                LDMATRIX_X4(ql[0], ql[1], ql[2], ql[3], ad + OQL);
                MMA_BF16(sacc[mi], qh, kbh[0], kbh[1]);
                MMA_BF16(sacc[mi], ql, kbh[0], kbh[1]);
                MMA_BF16(sacc[mi], qh, kbl[0], kbl[1]);
            }
        }
        #pragma unroll
        for (int mi = 0; mi < 4; mi++) {
            int r0 = mi * 16 + qrow;
            int c0 = n0 + qcol;
            float v0 = sacc[mi][0] * SCALE_;
            float v1 = sacc[mi][1] * SCALE_;
            float v2 = sacc[mi][2] * SCALE_;
            float v3 = sacc[mi][3] * SCALE_;
            if (selfb) {
                if (c0 > r0)         v0 = NEG_;
                if (c0 + 1 > r0)     v1 = NEG_;
                if (c0 > r0 + 8)     v2 = NEG_;
                if (c0 + 1 > r0 + 8) v3 = NEG_;
            }
            *(float2*)&Sx[r0 * 68 + c0]       = make_float2(v0, v1);
            *(float2*)&Sx[(r0 + 8) * 68 + c0] = make_float2(v2, v3);
        }
        __syncthreads();

        {
            const int r = tid >> 2, cg = tid & 3;
            float mold = mrw[r];
            float vals[16];
            float mx = -3.0e38f;
            #pragma unroll
            for (int j = 0; j < 16; j++) {
                vals[j] = Sx[r * 68 + cg * 16 + j];
                mx = fmaxf(mx, vals[j]);
            }
            mx = fmaxf(mx, __shfl_xor_sync(0xffffffffu, mx, 1));
            mx = fmaxf(mx, __shfl_xor_sync(0xffffffffu, mx, 2));
            float mnew = fmaxf(mold, mx);
            float al = __expf(mold - mnew);
            float ls = 0.f;
            #pragma unroll
            for (int j = 0; j < 16; j++) {
                float p = __expf(vals[j] - mnew);
                ls += p;
                __nv_bfloat16 phv = __float2bfloat16_rn(p);
                Ph[r * 72 + cg * 16 + j] = phv;
                Pl[r * 72 + cg * 16 + j] =
                    __float2bfloat16_rn(p - __bfloat162float(phv));
            }
            ls += __shfl_xor_sync(0xffffffffu, ls, 1);
            ls += __shfl_xor_sync(0xffffffffu, ls, 2);
            if (cg == 0) {
                mrw[r] = mnew;
                lrw[r] = lrw[r] * al + ls;
                alf[r] = al;
            }
        }
        __syncthreads();

        {
            float al0 = alf[miw * 16 + qrow];
            float al1 = alf[miw * 16 + qrow + 8];
            #pragma unroll
            for (int nt = 0; nt < 8; nt++) {
                accO[nt][0] *= al0; accO[nt][1] *= al0;
                accO[nt][2] *= al1; accO[nt][3] *= al1;
            }
            #pragma unroll
            for (int kk = 0; kk < 4; kk++) {
                uint32_t ph[4], pl[4];
                uint32_t ap = sb + ((uint32_t)(miw * 16) + arow) * 144 +
                              (uint32_t)(kk * 32) + acolb;
                LDMATRIX_X4(ph[0], ph[1], ph[2], ph[3], ap + OPH);
                LDMATRIX_X4(pl[0], pl[1], pl[2], pl[3], ap + OPL);
                uint32_t vrow = sb + ((uint32_t)(kk * 16) + arow) * 272;
                #pragma unroll
                for (int nj = 0; nj < 4; nj++) {
                    uint32_t vh[4], vl[4];
                    uint32_t ad = vrow + (uint32_t)((nhalf + nj * 16) * 2) + acolb;
                    LDMATRIX_X4T(vh[0], vh[1], vh[2], vh[3], ad + OVH);
                    LDMATRIX_X4T(vl[0], vl[1], vl[2], vl[3], ad + OVL);
                    MMA_BF16(accO[2 * nj],     ph, vh[0], vh[1]);
                    MMA_BF16(accO[2 * nj],     pl, vh[0], vh[1]);
                    MMA_BF16(accO[2 * nj],     ph, vl[0], vl[1]);
                    MMA_BF16(accO[2 * nj + 1], ph, vh[2], vh[3]);
                    MMA_BF16(accO[2 * nj + 1], pl, vh[2], vh[3]);
                    MMA_BF16(accO[2 * nj + 1], ph, vl[2], vl[3]);
                }
            }
        }
    }
    __syncthreads();

    // ---- epilogue: normalize, emit fp16 hi + residual lo ----
    {
        int r0 = miw * 16 + qrow;
        float linv0 = 1.0f / lrw[r0];
        float linv1 = 1.0f / lrw[r0 + 8];
        size_t base0 = (tok0 + r0) * HID_ + h * D_ + nhalf;
        size_t base1 = (tok0 + r0 + 8) * HID_ + h * D_ + nhalf;
        #pragma unroll
        for (int nt = 0; nt < 8; nt++) {
            int cn = nt * 8 + qcol;
            float o0 = accO[nt][0] * linv0, o1 = accO[nt][1] * linv0;
            float o2 = accO[nt][2] * linv1, o3 = accO[nt][3] * linv1;
            __half h0 = __float2half_rn(o0);
            __half h1 = __float2half_rn(o1);
            __half h2 = __float2half_rn(o2);
            __half h3 = __float2half_rn(o3);
            *(__half2*)(outh + base0 + cn) = __halves2half2(h0, h1);
            *(__half2*)(outh + base1 + cn) = __halves2half2(h2, h3);
            *(__half2*)(outl + base0 + cn) = __halves2half2(
                __float2half_rn(o0 - __half2float(h0)),
                __float2half_rn(o1 - __half2float(h1)));
            *(__half2*)(outl + base1 + cn) = __halves2half2(
                __float2half_rn(o2 - __half2float(h2)),
                __float2half_rn(o3 - __half2float(h3)));
        }
    }
}

// ---------------------------------------------------------------------------
extern "C" void kernel_launch(void* const* d_in, const int* in_sizes, int n_in,
                              void* d_out, int out_size)
{
    const float* hs = (const float*)d_in[0];
    const float* cs = (const float*)d_in[1];
    const float* sn = (const float*)d_in[2];
    const float* Wq = (const float*)d_in[3];
    const float* Wk = (const float*)d_in[4];
    const float* Wv = (const float*)d_in[5];
    const float* Wo = (const float*)d_in[6];
    float* out = (float*)d_out;

    float* qkv;
    __half *hsh, *hsl, *w1h, *w2h, *ath, *atl;
    cudaGetSymbolAddress((void**)&qkv, g_qkv);
    cudaGetSymbolAddress((void**)&hsh, g_hs_hi);
    cudaGetSymbolAddress((void**)&hsl, g_hs_lo);
    cudaGetSymbolAddress((void**)&w1h, g_w1_hi);
    cudaGetSymbolAddress((void**)&w2h, g_w2_hi);
    cudaGetSymbolAddress((void**)&ath, g_at_hi);
    cudaGetSymbolAddress((void**)&atl, g_at_lo);

    cudaFuncSetAttribute(gemm_f16x2, cudaFuncAttributeMaxDynamicSharedMemorySize,
                         GEMM_SMEM);
    cudaFuncSetAttribute(attn_kernel, cudaFuncAttributeMaxDynamicSharedMemorySize,
                         ATTN_SMEM);

    const int nHS  = MTOT * HID_;
    const int nWq  = HID_ * HID_;
    const int nWkv = 512 * HID_;

    cvt_kernel<<<nHS / 2048, 256>>>(hs, hsh, hsl, nHS);
    cvt_hi_kernel<<<nWq / 2048, 256>>>(Wq, w1h, nWq);
    cvt_hi_kernel<<<nWkv / 2048, 256>>>(Wk, w1h + (size_t)2048 * HID_, nWkv);
    cvt_hi_kernel<<<nWkv / 2048, 256>>>(Wv, w1h + (size_t)2560 * HID_, nWkv);
    cvt_hi_kernel<<<nWq / 2048, 256>>>(Wo, w2h, nWq);

    // QKV projection (fp16 2-term)
    gemm_f16x2<<<dim3(QKVN_ / 128, MTOT / 128), 256, GEMM_SMEM>>>(
        hsh, hsl, w1h, qkv, HID_, QKVN_);

    // RoPE
    rope_kernel<<<(MTOT * 20) / 8, 256>>>(qkv, cs, sn);

    // Attention (emits fp16 hi/lo)
    attn_kernel<<<dim3(NB_, H_, B_), 256, ATTN_SMEM>>>(qkv, ath, atl);

    // Output projection (fp16 2-term)
    gemm_f16x2<<<dim3(HID_ / 128, MTOT / 128), 256, GEMM_SMEM>>>(
        ath, atl, w2h, out, HID_, HID_);
}

// round 8
// speedup vs baseline: 1.2200x; 1.2200x over previous
#include <cuda_runtime.h>
#include <cuda_bf16.h>
#include <math.h>
#include <stdint.h>

#define B_    2
#define T_    4096
#define HID_  2048
#define H_    16
#define HKV_  4
#define D_    128
#define NB_   64
#define QKVN_ 3072
#define SCALE_ 0.088388347648318447f
#define NEG_  (-1.0e9f)
#define MTOT  (B_*T_)   // 8192

// ---------------- scratch ----------------------------------------------------
__device__ float g_qkv[(size_t)MTOT * QKVN_];
__device__ __nv_bfloat16 g_hs_hi[(size_t)MTOT*HID_];
__device__ __nv_bfloat16 g_hs_lo[(size_t)MTOT*HID_];
__device__ __nv_bfloat16 g_w1_hi[(size_t)QKVN_*HID_];
__device__ __nv_bfloat16 g_w1_lo[(size_t)QKVN_*HID_];
__device__ __nv_bfloat16 g_w2_hi[(size_t)HID_*HID_];
__device__ __nv_bfloat16 g_w2_lo[(size_t)HID_*HID_];
__device__ __nv_bfloat16 g_at_hi[(size_t)MTOT*HID_];
__device__ __nv_bfloat16 g_at_lo[(size_t)MTOT*HID_];

// ---------------- PTX helpers ----------------------------------------------
__device__ __forceinline__ uint32_t smem_u32(const void* p) {
    uint32_t a;
    asm("{ .reg .u64 t; cvta.to.shared.u64 t, %1; cvt.u32.u64 %0, t; }"
        : "=r"(a) : "l"(p));
    return a;
}

#define CP_ASYNC16(dst, src) \
    asm volatile("cp.async.cg.shared.global [%0], [%1], 16;\n" \
                 :: "r"(dst), "l"(src))
#define CP_COMMIT() asm volatile("cp.async.commit_group;\n" ::: "memory")
#define CP_WAIT(n)  asm volatile("cp.async.wait_group %0;\n" :: "n"(n) : "memory")

#define LDMATRIX_X4(r0, r1, r2, r3, addr) \
    asm volatile("ldmatrix.sync.aligned.m8n8.x4.shared.b16 {%0,%1,%2,%3}, [%4];" \
                 : "=r"(r0), "=r"(r1), "=r"(r2), "=r"(r3) : "r"(addr))

#define LDMATRIX_X2(r0, r1, addr) \
    asm volatile("ldmatrix.sync.aligned.m8n8.x2.shared.b16 {%0,%1}, [%2];" \
                 : "=r"(r0), "=r"(r1) : "r"(addr))

#define LDMATRIX_X4T(r0, r1, r2, r3, addr) \
    asm volatile("ldmatrix.sync.aligned.m8n8.x4.trans.shared.b16 {%0,%1,%2,%3}, [%4];" \
                 : "=r"(r0), "=r"(r1), "=r"(r2), "=r"(r3) : "r"(addr))

// NOTE: non-volatile — register-pure, lets the compiler schedule/interleave.
#define MMA_BF16(d, a, b0, b1) \
    asm("mma.sync.aligned.m16n8k16.row.col.f32.bf16.bf16.f32 " \
        "{%0,%1,%2,%3}, {%4,%5,%6,%7}, {%8,%9}, {%0,%1,%2,%3};" \
        : "+f"((d)[0]), "+f"((d)[1]), "+f"((d)[2]), "+f"((d)[3]) \
        : "r"((a)[0]), "r"((a)[1]), "r"((a)[2]), "r"((a)[3]), \
          "r"(b0), "r"(b1))

// float4 -> bf16 hi x4 + lo x4
__device__ __forceinline__ void cvt4(float4 v, uint2& H, uint2& L) {
    float a[4] = {v.x, v.y, v.z, v.w};
    __nv_bfloat16 h[4], l[4];
    #pragma unroll
    for (int j = 0; j < 4; j++) {
        h[j] = __float2bfloat16_rn(a[j]);
        l[j] = __float2bfloat16_rn(a[j] - __bfloat162float(h[j]));
    }
    union { __nv_bfloat162 b2[2]; uint2 u; } uh, ul;
    uh.b2[0] = __halves2bfloat162(h[0], h[1]);
    uh.b2[1] = __halves2bfloat162(h[2], h[3]);
    ul.b2[0] = __halves2bfloat162(l[0], l[1]);
    ul.b2[1] = __halves2bfloat162(l[2], l[3]);
    H = uh.u; L = ul.u;
}

// ---------------------------------------------------------------------------
// fp32 -> bf16 hi + residual lo, 8 elements/thread
// ---------------------------------------------------------------------------
__global__ void cvt_kernel(const float* __restrict__ in,
                           __nv_bfloat16* __restrict__ hi,
                           __nv_bfloat16* __restrict__ lo, int n)
{
    size_t i = ((size_t)blockIdx.x * blockDim.x + threadIdx.x) * 8;
    if (i >= (size_t)n) return;
    uint2 H0, L0, H1, L1;
    cvt4(*(const float4*)(in + i),     H0, L0);
    cvt4(*(const float4*)(in + i + 4), H1, L1);
    *(uint4*)(hi + i) = make_uint4(H0.x, H0.y, H1.x, H1.y);
    *(uint4*)(lo + i) = make_uint4(L0.x, L0.y, L1.x, L1.y);
}

// ---------------------------------------------------------------------------
// mma.sync bf16 GEMM: C = A*B^T, 3-term hi/lo (Ah*Bh + Al*Bh + Ah*Bl).
// Term-major MMA emission: 4 independent accumulator chains between reuses.
// ---------------------------------------------------------------------------
#define GEMM_SMEM (3 * 65536)

__global__ void __launch_bounds__(256, 1) gemm_bf16x3(
    const __nv_bfloat16* __restrict__ Ah, const __nv_bfloat16* __restrict__ Al,
    const __nv_bfloat16* __restrict__ Bh, const __nv_bfloat16* __restrict__ Bl,
    float* __restrict__ C, int K, int ldc)
{
    extern __shared__ char smem[];
    const int tid  = threadIdx.x;
    const int lane = tid & 31;
    const int wid  = tid >> 5;
    const int m0 = blockIdx.y * 128;
    const int n0 = blockIdx.x * 128;
    const int warpM = (wid >> 2) * 64;
    const int warpN = (wid & 3) * 32;

    const uint32_t sb = smem_u32(smem);

    uint32_t soff[4]; uint32_t grow[4]; uint32_t gcol[4];
    #pragma unroll
    for (int t = 0; t < 4; t++) {
        int idx = tid + t * 256;
        int row = idx >> 3, u = idx & 7;
        uint32_t bo = (uint32_t)(row * 128 + u * 16);
        soff[t] = bo ^ ((bo >> 3) & 0x70);
        grow[t] = (uint32_t)row;
        gcol[t] = (uint32_t)(u * 16);
    }

    const int NCH = K >> 6;
    const size_t rs = (size_t)K * 2;
    const char* pAh = (const char*)(Ah + (size_t)m0 * K);
    const char* pAl = (const char*)(Al + (size_t)m0 * K);
    const char* pBh = (const char*)(Bh + (size_t)n0 * K);
    const char* pBl = (const char*)(Bl + (size_t)n0 * K);

    auto load_chunk = [&](int c) {
        uint32_t base = sb + (uint32_t)(c % 3) * 65536u;
        size_t co = (size_t)c * 128;
        #pragma unroll
        for (int t = 0; t < 4; t++) {
            size_t go = (size_t)grow[t] * rs + co + gcol[t];
            CP_ASYNC16(base +          soff[t], pAh + go);
            CP_ASYNC16(base + 16384u + soff[t], pAl + go);
            CP_ASYNC16(base + 32768u + soff[t], pBh + go);
            CP_ASYNC16(base + 49152u + soff[t], pBl + go);
        }
        CP_COMMIT();
    };

    const uint32_t lrow  = (uint32_t)(lane & 15);
    const uint32_t lcolb = (uint32_t)((lane >> 4) * 16);
    const uint32_t cx    = ((uint32_t)lrow & 7) << 4;
    const uint32_t aRowOff = (uint32_t)(warpM + lrow) * 128;
    const uint32_t bRowOff = (uint32_t)(warpN + lrow) * 128;

    float d[4][4][4];
    #pragma unroll
    for (int mi = 0; mi < 4; mi++)
        #pragma unroll
        for (int ni = 0; ni < 4; ni++)
            #pragma unroll
            for (int r = 0; r < 4; r++) d[mi][ni][r] = 0.f;

    load_chunk(0);
    if (NCH > 1) load_chunk(1);
    if (NCH > 2) load_chunk(2);

    for (int c = 0; c < NCH; c++) {
        const int rem = NCH - 1 - c;
        if (rem >= 2)      { CP_WAIT(2); }
        else if (rem == 1) { CP_WAIT(1); }
        else               { CP_WAIT(0); }
        __syncthreads();

        const uint32_t base = sb + (uint32_t)(c % 3) * 65536u;
        #pragma unroll
        for (int kk = 0; kk < 4; kk++) {
            const uint32_t cb = ((uint32_t)(kk * 32) + lcolb) ^ cx;
            uint32_t bh[2][4], bl[2][4];
            #pragma unroll
            for (int pj = 0; pj < 2; pj++) {
                uint32_t ab = base + bRowOff + (uint32_t)pj * 2048 + cb;
                LDMATRIX_X4(bh[pj][0], bh[pj][1], bh[pj][2], bh[pj][3], ab + 32768u);
                LDMATRIX_X4(bl[pj][0], bl[pj][1], bl[pj][2], bl[pj][3], ab + 49152u);
            }
            #pragma unroll
            for (int mi = 0; mi < 4; mi++) {
                uint32_t ah[4], al2[4];
                uint32_t aa = base + aRowOff + (uint32_t)mi * 2048 + cb;
                LDMATRIX_X4(ah[0], ah[1], ah[2], ah[3], aa);
                LDMATRIX_X4(al2[0], al2[1], al2[2], al2[3], aa + 16384u);
                // term-major: 4 independent chains between accumulator reuses
                #pragma unroll
                for (int ni = 0; ni < 4; ni++) {
                    const int pj = ni >> 1, j = ni & 1;
                    MMA_BF16(d[mi][ni], ah, bh[pj][j], bh[pj][j + 2]);
                }
                #pragma unroll
                for (int ni = 0; ni < 4; ni++) {
                    const int pj = ni >> 1, j = ni & 1;
                    MMA_BF16(d[mi][ni], al2, bh[pj][j], bh[pj][j + 2]);
                }
                #pragma unroll
                for (int ni = 0; ni < 4; ni++) {
                    const int pj = ni >> 1, j = ni & 1;
                    MMA_BF16(d[mi][ni], ah, bl[pj][j], bl[pj][j + 2]);
                }
            }
        }
        __syncthreads();
        if (c + 3 < NCH) load_chunk(c + 3);
    }

    #pragma unroll
    for (int mi = 0; mi < 4; mi++) {
        const int r0 = m0 + warpM + mi * 16 + (lane >> 2);
        #pragma unroll
        for (int ni = 0; ni < 4; ni++) {
            const int cn = n0 + warpN + ni * 8 + (lane & 3) * 2;
            *(float2*)(C + (size_t)r0 * ldc + cn) =
                make_float2(d[mi][ni][0], d[mi][ni][1]);
            *(float2*)(C + (size_t)(r0 + 8) * ldc + cn) =
                make_float2(d[mi][ni][2], d[mi][ni][3]);
        }
    }
}

// ---------------------------------------------------------------------------
// RoPE in-place on g_qkv
// ---------------------------------------------------------------------------
__global__ void rope_kernel(float* __restrict__ qkv,
                            const float* __restrict__ cosb,
                            const float* __restrict__ sinb)
{
    const int gw   = (blockIdx.x * blockDim.x + threadIdx.x) >> 5;
    const int lane = threadIdx.x & 31;
    const int tok  = gw / 20;
    const int hh   = gw % 20;
    if (tok >= MTOT) return;

    float* base = qkv + (size_t)tok * QKVN_ +
                  (hh < 16 ? hh * D_ : 2048 + (hh - 16) * D_);
    const float* cr = cosb + (size_t)tok * 64;
    const float* sr = sinb + (size_t)tok * 64;

    float x1 = base[lane], x2 = base[lane + 32];
    float c1 = cr[lane],  s1 = sr[lane];
    float c2 = cr[lane + 32], s2 = sr[lane + 32];
    base[lane]      = x1 * c1 - x2 * s1;
    base[lane + 32] = x2 * c2 + x1 * s2;
}

// ---------------------------------------------------------------------------
// Tensor-core block-sparse attention, bf16 hi/lo 3-term, fp32 softmax.
// Interleaved MMA emission (term-major) for latency hiding.
// ---------------------------------------------------------------------------
#define OQH 0
#define OQL 17408
#define OKH 34816
#define OKL 52224
#define OVH 69632
#define OVL 87040
#define OSX 104448          // fp32 [64][68]
#define OPH 121856          // bf16 [64][72]
#define OPL 131072
#define OALF 140288
#define OMRW 140544
#define OLRW 140800
#define ATTN_SMEM 141056

__global__ void __launch_bounds__(256) attn_kernel(const float* __restrict__ qkv,
                                                   __nv_bfloat16* __restrict__ outh,
                                                   __nv_bfloat16* __restrict__ outl)
{
    extern __shared__ char smc[];
    const uint32_t sb = smem_u32(smc);
    float* Sx  = (float*)(smc + OSX);
    __nv_bfloat16* Ph = (__nv_bfloat16*)(smc + OPH);
    __nv_bfloat16* Pl = (__nv_bfloat16*)(smc + OPL);
    float* alf = (float*)(smc + OALF);
    float* mrw = (float*)(smc + OMRW);
    float* lrw = (float*)(smc + OLRW);

    const int tid  = threadIdx.x;
    const int lane = tid & 31;
    const int wid  = tid >> 5;
    const int iblk = blockIdx.x;
    const int h    = blockIdx.y;
    const int b    = blockIdx.z;
    const int hk   = h >> 2;
    const size_t tok0 = (size_t)b * T_ + (size_t)iblk * 64;

    const float* qg = qkv + tok0 * QKVN_ + h * D_;
    for (int f = tid; f < 2048; f += 256) {
        int r = f >> 5, c4 = (f & 31) * 4;
        uint2 Hv, Lv;
        cvt4(*(const float4*)(qg + (size_t)r * QKVN_ + c4), Hv, Lv);
        uint32_t off = (uint32_t)(r * 272 + c4 * 2);
        *(uint2*)(smc + OQH + off) = Hv;
        *(uint2*)(smc + OQL + off) = Lv;
    }
    if (tid < 64) { mrw[tid] = -3.0e38f; lrw[tid] = 0.f; }

    const uint32_t arow  = (uint32_t)(lane & 15);
    const uint32_t acolb = (uint32_t)((lane >> 4) * 16);
    const int qrow = lane >> 2;
    const int qcol = (lane & 3) * 2;

    const int n0 = wid * 8;
    const int miw   = wid >> 1;
    const int nhalf = (wid & 1) * 64;

    float accO[8][4];
    #pragma unroll
    for (int nt = 0; nt < 8; nt++)
        #pragma unroll
        for (int r = 0; r < 4; r++) accO[nt][r] = 0.f;

    for (int s = 0; s < 9; s++) {
        int kb = (s == 0) ? 0 : iblk - 8 + s;
        if (s > 0 && kb <= 0) continue;
        const bool selfb = (kb == iblk);

        __syncthreads();

        const size_t ktok = (size_t)b * T_ + (size_t)kb * 64;
        const float* kg = qkv + ktok * QKVN_ + 2048 + hk * D_;
        const float* vg = kg + 512;
        for (int f = tid; f < 2048; f += 256) {
            int r = f >> 5, c4 = (f & 31) * 4;
            uint32_t off = (uint32_t)(r * 272 + c4 * 2);
            uint2 Hv, Lv;
            cvt4(*(const float4*)(kg + (size_t)r * QKVN_ + c4), Hv, Lv);
            *(uint2*)(smc + OKH + off) = Hv;
            *(uint2*)(smc + OKL + off) = Lv;
            cvt4(*(const float4*)(vg + (size_t)r * QKVN_ + c4), Hv, Lv);
            *(uint2*)(smc + OVH + off) = Hv;
            *(uint2*)(smc + OVL + off) = Lv;
        }
        __syncthreads();

        // ---- QK^T, term-major (4 independent chains per round) ----
        float sacc[4][4];
        #pragma unroll
        for (int mi = 0; mi < 4; mi++)
            #pragma unroll
            for (int r = 0; r < 4; r++) sacc[mi][r] = 0.f;

        #pragma unroll
        for (int kk = 0; kk < 8; kk++) {
            uint32_t kbh[2], kbl[2];
            {
                uint32_t r = (uint32_t)(n0 + (lane & 7));
                uint32_t cb = (uint32_t)(kk * 32 + ((lane >> 3) & 1) * 16);
                uint32_t ad = sb + r * 272 + cb;
                LDMATRIX_X2(kbh[0], kbh[1], ad + OKH);
                LDMATRIX_X2(kbl[0], kbl[1], ad + OKL);
            }
            uint32_t qh[4][4], ql[4][4];
            #pragma unroll
            for (int mi = 0; mi < 4; mi++) {
                uint32_t ad = sb + ((uint32_t)(mi * 16) + arow) * 272 +
                              (uint32_t)(kk * 32) + acolb;
                LDMATRIX_X4(qh[mi][0], qh[mi][1], qh[mi][2], qh[mi][3], ad + OQH);
                LDMATRIX_X4(ql[mi][0], ql[mi][1], ql[mi][2], ql[mi][3], ad + OQL);
            }
            #pragma unroll
            for (int mi = 0; mi < 4; mi++) MMA_BF16(sacc[mi], qh[mi], kbh[0], kbh[1]);
            #pragma unroll
            for (int mi = 0; mi < 4; mi++) MMA_BF16(sacc[mi], ql[mi], kbh[0], kbh[1]);
            #pragma unroll
            for (int mi = 0; mi < 4; mi++) MMA_BF16(sacc[mi], qh[mi], kbl[0], kbl[1]);
        }
        #pragma unroll
        for (int mi = 0; mi < 4; mi++) {
            int r0 = mi * 16 + qrow;
            int c0 = n0 + qcol;
            float v0 = sacc[mi][0] * SCALE_;
            float v1 = sacc[mi][1] * SCALE_;
            float v2 = sacc[mi][2] * SCALE_;
            float v3 = sacc[mi][3] * SCALE_;
            if (selfb) {
                if (c0 > r0)         v0 = NEG_;
                if (c0 + 1 > r0)     v1 = NEG_;
                if (c0 > r0 + 8)     v2 = NEG_;
                if (c0 + 1 > r0 + 8) v3 = NEG_;
            }
            *(float2*)&Sx[r0 * 68 + c0]       = make_float2(v0, v1);
            *(float2*)&Sx[(r0 + 8) * 68 + c0] = make_float2(v2, v3);
        }
        __syncthreads();

        {
            const int r = tid >> 2, cg = tid & 3;
            float mold = mrw[r];
            float vals[16];
            float mx = -3.0e38f;
            #pragma unroll
            for (int j = 0; j < 16; j++) {
                vals[j] = Sx[r * 68 + cg * 16 + j];
                mx = fmaxf(mx, vals[j]);
            }
            mx = fmaxf(mx, __shfl_xor_sync(0xffffffffu, mx, 1));
            mx = fmaxf(mx, __shfl_xor_sync(0xffffffffu, mx, 2));
            float mnew = fmaxf(mold, mx);
            float al = __expf(mold - mnew);
            float ls = 0.f;
            #pragma unroll
            for (int j = 0; j < 16; j++) {
                float p = __expf(vals[j] - mnew);
                ls += p;
                __nv_bfloat16 phv = __float2bfloat16_rn(p);
                Ph[r * 72 + cg * 16 + j] = phv;
                Pl[r * 72 + cg * 16 + j] =
                    __float2bfloat16_rn(p - __bfloat162float(phv));
            }
            ls += __shfl_xor_sync(0xffffffffu, ls, 1);
            ls += __shfl_xor_sync(0xffffffffu, ls, 2);
            if (cg == 0) {
                mrw[r] = mnew;
                lrw[r] = lrw[r] * al + ls;
                alf[r] = al;
            }
        }
        __syncthreads();

        // ---- PV, term-major (8 independent chains per round) ----
        {
            float al0 = alf[miw * 16 + qrow];
            float al1 = alf[miw * 16 + qrow + 8];
            #pragma unroll
            for (int nt = 0; nt < 8; nt++) {
                accO[nt][0] *= al0; accO[nt][1] *= al0;
                accO[nt][2] *= al1; accO[nt][3] *= al1;
            }
            #pragma unroll
            for (int kk = 0; kk < 4; kk++) {
                uint32_t ph[4], pl[4];
                uint32_t ap = sb + ((uint32_t)(miw * 16) + arow) * 144 +
                              (uint32_t)(kk * 32) + acolb;
                LDMATRIX_X4(ph[0], ph[1], ph[2], ph[3], ap + OPH);
                LDMATRIX_X4(pl[0], pl[1], pl[2], pl[3], ap + OPL);
                uint32_t vrow = sb + ((uint32_t)(kk * 16) + arow) * 272;
                uint32_t vh[4][4], vl[4][4];
                #pragma unroll
                for (int nj = 0; nj < 4; nj++) {
                    uint32_t ad = vrow + (uint32_t)((nhalf + nj * 16) * 2) + acolb;
                    LDMATRIX_X4T(vh[nj][0], vh[nj][1], vh[nj][2], vh[nj][3], ad + OVH);
                    LDMATRIX_X4T(vl[nj][0], vl[nj][1], vl[nj][2], vl[nj][3], ad + OVL);
                }
                #pragma unroll
                for (int nj = 0; nj < 4; nj++) {
                    MMA_BF16(accO[2 * nj],     ph, vh[nj][0], vh[nj][1]);
                    MMA_BF16(accO[2 * nj + 1], ph, vh[nj][2], vh[nj][3]);
                }
                #pragma unroll
                for (int nj = 0; nj < 4; nj++) {
                    MMA_BF16(accO[2 * nj],     pl, vh[nj][0], vh[nj][1]);
                    MMA_BF16(accO[2 * nj + 1], pl, vh[nj][2], vh[nj][3]);
                }
                #pragma unroll
                for (int nj = 0; nj < 4; nj++) {
                    MMA_BF16(accO[2 * nj],     ph, vl[nj][0], vl[nj][1]);
                    MMA_BF16(accO[2 * nj + 1], ph, vl[nj][2], vl[nj][3]);
                }
            }
        }
    }
    __syncthreads();

    {
        int r0 = miw * 16 + qrow;
        float linv0 = 1.0f / lrw[r0];
        float linv1 = 1.0f / lrw[r0 + 8];
        size_t base0 = (tok0 + r0) * HID_ + h * D_ + nhalf;
        size_t base1 = (tok0 + r0 + 8) * HID_ + h * D_ + nhalf;
        #pragma unroll
        for (int nt = 0; nt < 8; nt++) {
            int cn = nt * 8 + qcol;
            float o0 = accO[nt][0] * linv0, o1 = accO[nt][1] * linv0;
            float o2 = accO[nt][2] * linv1, o3 = accO[nt][3] * linv1;
            __nv_bfloat16 h0 = __float2bfloat16_rn(o0);
            __nv_bfloat16 h1 = __float2bfloat16_rn(o1);
            __nv_bfloat16 h2 = __float2bfloat16_rn(o2);
            __nv_bfloat16 h3 = __float2bfloat16_rn(o3);
            *(__nv_bfloat162*)(outh + base0 + cn) = __halves2bfloat162(h0, h1);
            *(__nv_bfloat162*)(outh + base1 + cn) = __halves2bfloat162(h2, h3);
            *(__nv_bfloat162*)(outl + base0 + cn) = __halves2bfloat162(
                __float2bfloat16_rn(o0 - __bfloat162float(h0)),
                __float2bfloat16_rn(o1 - __bfloat162float(h1)));
            *(__nv_bfloat162*)(outl + base1 + cn) = __halves2bfloat162(
                __float2bfloat16_rn(o2 - __bfloat162float(h2)),
                __float2bfloat16_rn(o3 - __bfloat162float(h3)));
        }
    }
}

// ---------------------------------------------------------------------------
extern "C" void kernel_launch(void* const* d_in, const int* in_sizes, int n_in,
                              void* d_out, int out_size)
{
    const float* hs = (const float*)d_in[0];
    const float* cs = (const float*)d_in[1];
    const float* sn = (const float*)d_in[2];
    const float* Wq = (const float*)d_in[3];
    const float* Wk = (const float*)d_in[4];
    const float* Wv = (const float*)d_in[5];
    const float* Wo = (const float*)d_in[6];
    float* out = (float*)d_out;

    float* qkv;
    __nv_bfloat16 *hsh, *hsl, *w1h, *w1l, *w2h, *w2l, *ath, *atl;
    cudaGetSymbolAddress((void**)&qkv, g_qkv);
    cudaGetSymbolAddress((void**)&hsh, g_hs_hi);
    cudaGetSymbolAddress((void**)&hsl, g_hs_lo);
    cudaGetSymbolAddress((void**)&w1h, g_w1_hi);
    cudaGetSymbolAddress((void**)&w1l, g_w1_lo);
    cudaGetSymbolAddress((void**)&w2h, g_w2_hi);
    cudaGetSymbolAddress((void**)&w2l, g_w2_lo);
    cudaGetSymbolAddress((void**)&ath, g_at_hi);
    cudaGetSymbolAddress((void**)&atl, g_at_lo);

    cudaFuncSetAttribute(gemm_bf16x3, cudaFuncAttributeMaxDynamicSharedMemorySize,
                         GEMM_SMEM);
    cudaFuncSetAttribute(attn_kernel, cudaFuncAttributeMaxDynamicSharedMemorySize,
                         ATTN_SMEM);

    const int nHS  = MTOT * HID_;
    const int nWq  = HID_ * HID_;
    const int nWkv = 512 * HID_;

    cvt_kernel<<<nHS / 2048, 256>>>(hs, hsh, hsl, nHS);
    cvt_kernel<<<nWq / 2048, 256>>>(Wq, w1h, w1l, nWq);
    cvt_kernel<<<nWkv / 2048, 256>>>(Wk, w1h + (size_t)2048 * HID_,
                                         w1l + (size_t)2048 * HID_, nWkv);
    cvt_kernel<<<nWkv / 2048, 256>>>(Wv, w1h + (size_t)2560 * HID_,
                                         w1l + (size_t)2560 * HID_, nWkv);
    cvt_kernel<<<nWq / 2048, 256>>>(Wo, w2h, w2l, nWq);

    // QKV projection
    gemm_bf16x3<<<dim3(QKVN_ / 128, MTOT / 128), 256, GEMM_SMEM>>>(
        hsh, hsl, w1h, w1l, qkv, HID_, QKVN_);

    // RoPE
    rope_kernel<<<(MTOT * 20) / 8, 256>>>(qkv, cs, sn);

    // Attention (emits bf16 hi/lo)
    attn_kernel<<<dim3(NB_, H_, B_), 256, ATTN_SMEM>>>(qkv, ath, atl);

    // Output projection
    gemm_bf16x3<<<dim3(HID_ / 128, MTOT / 128), 256, GEMM_SMEM>>>(
        ath, atl, w2h, w2l, out, HID_, HID_);
}